// round 4
// baseline (speedup 1.0000x reference)
#include <cuda_runtime.h>
#include <cstdint>

#define PNUM 8
#define DDIM 512
#define ADIM 64
#define XDIM 576
#define HDIM 1024
#define BCAP 16384
#define MAXT 136

// ---------------- device scratch ----------------
__device__ int d_cursor[PNUM];     // atomic cursors; end state = per-policy counts
__device__ int d_is64;
__device__ int d_row_id[PNUM * BCAP];
__device__ __align__(128) float d_hbuf[(size_t)MAXT * 128 * HDIM];        // 71 MB
__device__ __align__(128) float d_w1t[(size_t)PNUM * HDIM * XDIM];        // [p][n][k], tf32-rounded
__device__ __align__(128) float d_w2t[(size_t)PNUM * DDIM * HDIM];        // [p][n][k], tf32-rounded

// ---------------- helpers ----------------
__device__ __forceinline__ void cpasync16(uint32_t dst, const void* src, int srcsz) {
    asm volatile("cp.async.cg.shared.global [%0], [%1], 16, %2;\n"
                 :: "r"(dst), "l"(src), "r"(srcsz) : "memory");
}
#define CP_COMMIT() asm volatile("cp.async.commit_group;\n" ::: "memory")
#define CP_WAIT(n)  asm volatile("cp.async.wait_group " #n ";\n" ::: "memory")

__device__ __forceinline__ uint32_t smem_u32(const void* p) {
    uint32_t a;
    asm("{ .reg .u64 t; cvta.to.shared.u64 t, %1; cvt.u32.u64 %0, t; }" : "=r"(a) : "l"(p));
    return a;
}
__device__ __forceinline__ float tf32r(float x) {
    uint32_t u;
    asm("cvt.rn.tf32.f32 %0, %1;" : "=r"(u) : "f"(x));
    return __uint_as_float(u);
}
__device__ __forceinline__ uint32_t tf32u(float x) {
    uint32_t u;
    asm("cvt.rn.tf32.f32 %0, %1;" : "=r"(u) : "f"(x));
    return u;
}
__device__ __forceinline__ void ldsm4(uint32_t* r, uint32_t addr) {
    asm volatile("ldmatrix.sync.aligned.m8n8.x4.shared.b16 {%0,%1,%2,%3}, [%4];"
                 : "=r"(r[0]), "=r"(r[1]), "=r"(r[2]), "=r"(r[3]) : "r"(addr));
}
__device__ __forceinline__ void mma_tf32(float* c, const uint32_t* a, uint32_t b0, uint32_t b1) {
    asm volatile(
        "mma.sync.aligned.m16n8k8.row.col.f32.tf32.tf32.f32 "
        "{%0,%1,%2,%3}, {%4,%5,%6,%7}, {%8,%9}, {%0,%1,%2,%3};"
        : "+f"(c[0]), "+f"(c[1]), "+f"(c[2]), "+f"(c[3])
        : "r"(a[0]), "r"(a[1]), "r"(a[2]), "r"(a[3]), "r"(b0), "r"(b1));
}
__device__ __forceinline__ int get_pidx(const void* pi, int b) {
    if (d_is64) return (int)(((const long long*)pi)[b]);
    return ((const int*)pi)[b];
}

// ---------------- setup ----------------
__global__ void k_init(const int* pi32, int B) {
    int t = threadIdx.x;
    if (t < PNUM) d_cursor[t] = 0;
    if (t == 0) {
        int n = B < 64 ? B : 64;
        int is64 = 1;
        for (int i = 0; i < n; i++) {
            int lo = pi32[2 * i], hi = pi32[2 * i + 1];
            if (hi != 0 || lo < 0 || lo >= PNUM) { is64 = 0; break; }
        }
        d_is64 = is64;
    }
}
// one atomic per sample: position within policy region AND running count
__global__ void k_scan(const void* __restrict__ pi, int B) {
    int b = blockIdx.x * blockDim.x + threadIdx.x;
    if (b < B) {
        int p = get_pidx(pi, b);
        int pos = atomicAdd(&d_cursor[p], 1);
        d_row_id[p * BCAP + pos] = b;
    }
}

// Transpose + tf32-round weights:
// W1 [p][576k][1024n] -> d_w1t [p][1024n][576k];  W2 [p][1024k][512n] -> d_w2t [p][512n][1024k]
#define W1BLK (PNUM * 18 * 32)
#define W2BLK (PNUM * 32 * 16)
__global__ __launch_bounds__(256) void k_tw(const float* __restrict__ W1,
                                            const float* __restrict__ W2) {
    __shared__ float s[32][33];
    int bid = blockIdx.x;
    int tx = threadIdx.x & 31, ty = threadIdx.x >> 5;
    if (bid < W1BLK) {
        int p = bid / (18 * 32), r = bid % (18 * 32), rt = r / 32, ct = r % 32;
        const float* in = W1 + (size_t)p * XDIM * HDIM;
        float* out = d_w1t + (size_t)p * HDIM * XDIM;
        int r0 = rt * 32, c0 = ct * 32;
#pragma unroll
        for (int i = 0; i < 4; i++)
            s[ty + 8 * i][tx] = in[(size_t)(r0 + ty + 8 * i) * HDIM + c0 + tx];
        __syncthreads();
#pragma unroll
        for (int i = 0; i < 4; i++)
            out[(size_t)(c0 + ty + 8 * i) * XDIM + r0 + tx] = tf32r(s[tx][ty + 8 * i]);
    } else {
        int b2 = bid - W1BLK;
        int p = b2 / (32 * 16), r = b2 % (32 * 16), rt = r / 16, ct = r % 16;
        const float* in = W2 + (size_t)p * HDIM * DDIM;
        float* out = d_w2t + (size_t)p * DDIM * HDIM;
        int r0 = rt * 32, c0 = ct * 32;
#pragma unroll
        for (int i = 0; i < 4; i++)
            s[ty + 8 * i][tx] = in[(size_t)(r0 + ty + 8 * i) * DDIM + c0 + tx];
        __syncthreads();
#pragma unroll
        for (int i = 0; i < 4; i++)
            out[(size_t)(c0 + ty + 8 * i) * HDIM + r0 + tx] = tf32r(s[tx][ty + 8 * i]);
    }
}

// ---------------- SMEM layout ----------------
// A and B tiles: 128 rows x 32 k floats, row stride 36 (pad kills conflicts)
#define TSTRIDE 36
#define TBYTES  (128 * TSTRIDE * 4)   // 18432
#define STAGE   (2 * TBYTES)          // 36864
#define SMEM_TOTAL (2 * STAGE)        // 73728

// ---------------- fused tf32 GEMM (128x128 CTA tile, 4 warps of 64x64, BK=32) ----------------
template <int LAYER>
__global__ __launch_bounds__(128, 2) void k_mma(
    const float* __restrict__ latents, const float* __restrict__ actions,
    const float* __restrict__ bias, float* __restrict__ out)
{
    constexpr int KDIM = (LAYER == 1) ? XDIM : HDIM;
    constexpr int NDIM = (LAYER == 1) ? HDIM : DDIM;
    constexpr int KT   = KDIM / 32;

    extern __shared__ char smem[];
    __shared__ int rid_s[128];
    __shared__ int s_meta[3];   // p, vrows, ridbase
    const uint32_t sb = smem_u32(smem);
    const int tid = threadIdx.x;
    const int t = blockIdx.y;

    if (tid == 0) {
        int acc = 0, p = -1, lt = 0, c = 0;
#pragma unroll
        for (int q = 0; q < PNUM; q++) {
            int cq = d_cursor[q];
            int nt = (cq + 127) >> 7;
            if (p < 0 && t < acc + nt) { p = q; lt = t - acc; c = cq; }
            acc += nt;
        }
        s_meta[0] = p;
        if (p >= 0) {
            int rem = c - lt * 128;
            s_meta[1] = rem < 128 ? rem : 128;
            s_meta[2] = p * BCAP + lt * 128;
        }
    }
    __syncthreads();
    const int p = s_meta[0];
    if (p < 0) return;
    const int vrows = s_meta[1];
    const int ridbase = s_meta[2];
    const int n0 = blockIdx.x * 128;
    const int row0 = t * 128;   // compact h-buffer row base

    rid_s[tid] = (tid < vrows) ? d_row_id[ridbase + tid] : -1;
    __syncthreads();

    const float* __restrict__ Wt = (LAYER == 1)
        ? d_w1t + (size_t)p * HDIM * XDIM + (size_t)n0 * XDIM
        : d_w2t + (size_t)p * DDIM * HDIM + (size_t)n0 * HDIM;

    // ---- async tile loader: 128 rows x 8 segs for A and B ----
    auto load_chunk = [&](int chunk, int slot) {
        const int kc = chunk * 32;
        const uint32_t abase = sb + slot * STAGE;
        const uint32_t bbase = abase + TBYTES;
#pragma unroll
        for (int tt = 0; tt < 8; tt++) {
            int j = tid + tt * 128;
            int row = j >> 3, seg = j & 7;
            uint32_t dst = abase + row * (TSTRIDE * 4) + seg * 16;
            if (LAYER == 1) {
                int b = rid_s[row];
                int k = kc + seg * 4;
                const float* src; int sz;
                if (b < 0) { src = latents; sz = 0; }
                else if (k < DDIM) { src = latents + (size_t)b * DDIM + k; sz = 16; }
                else { src = actions + (size_t)b * ADIM + (k - DDIM); sz = 16; }
                cpasync16(dst, src, sz);
            } else {
                cpasync16(dst, d_hbuf + (size_t)(row0 + row) * HDIM + kc + seg * 4, 16);
            }
        }
#pragma unroll
        for (int tt = 0; tt < 8; tt++) {
            int j = tid + tt * 128;
            int row = j >> 3, seg = j & 7;
            cpasync16(bbase + row * (TSTRIDE * 4) + seg * 16,
                      Wt + (size_t)row * KDIM + kc + seg * 4, 16);
        }
        CP_COMMIT();
    };

    // ---- fragment geometry ----
    const int lane = tid & 31, warp = tid >> 5;
    const int wm = warp >> 1, wn = warp & 1;         // 2x2 warps, 64x64 each
    const int g = lane >> 2, tq = lane & 3;
    // ldmatrix per-thread byte offset (identical structure for A and B tiles)
    const uint32_t fo = ((uint32_t)(lane & 15) * TSTRIDE + ((lane & 16) >> 2)) * 4;
    const uint32_t ao = (uint32_t)(wm * 64) * TSTRIDE * 4 + fo;
    const uint32_t bo = (uint32_t)(wn * 64) * TSTRIDE * 4 + fo;

    float acc[4][8][4];
#pragma unroll
    for (int i = 0; i < 4; i++)
#pragma unroll
        for (int j = 0; j < 8; j++)
#pragma unroll
            for (int q = 0; q < 4; q++) acc[i][j][q] = 0.f;

    load_chunk(0, 0);

    for (int c = 0; c < KT; c++) {
        if (c + 1 < KT) { load_chunk(c + 1, (c + 1) & 1); CP_WAIT(1); }
        else            { CP_WAIT(0); }
        __syncthreads();

        const uint32_t Ab = sb + (c & 1) * STAGE;
        const uint32_t Bb = Ab + TBYTES;

#pragma unroll
        for (int ks = 0; ks < 4; ks++) {
            uint32_t a[4][4], b[4][4];
#pragma unroll
            for (int i = 0; i < 4; i++)
                ldsm4(a[i], Ab + ao + (uint32_t)(i * 16 * TSTRIDE + ks * 8) * 4);
            if (LAYER == 1) {
#pragma unroll
                for (int i = 0; i < 4; i++)
#pragma unroll
                    for (int q = 0; q < 4; q++)
                        a[i][q] = tf32u(__uint_as_float(a[i][q]));
            }
#pragma unroll
            for (int jj = 0; jj < 4; jj++)
                ldsm4(b[jj], Bb + bo + (uint32_t)(jj * 16 * TSTRIDE + ks * 8) * 4);
#pragma unroll
            for (int i = 0; i < 4; i++)
#pragma unroll
                for (int jj = 0; jj < 4; jj++) {
                    mma_tf32(acc[i][2 * jj],     a[i], b[jj][0], b[jj][2]);
                    mma_tf32(acc[i][2 * jj + 1], a[i], b[jj][1], b[jj][3]);
                }
        }
        __syncthreads();
    }

    // ---- epilogue ----
    const float* bp = bias + p * NDIM + n0;
    if (LAYER == 1) {
        float* hb = d_hbuf + (size_t)row0 * HDIM + n0;
#pragma unroll
        for (int j = 0; j < 8; j++) {
            int col = wn * 64 + j * 8 + 2 * tq;
            float bx = bp[col], by = bp[col + 1];
#pragma unroll
            for (int i = 0; i < 4; i++) {
                int r0 = wm * 64 + i * 16 + g;
                float2 v0 = make_float2(tf32r(fmaxf(acc[i][j][0] + bx, 0.f)),
                                        tf32r(fmaxf(acc[i][j][1] + by, 0.f)));
                float2 v1 = make_float2(tf32r(fmaxf(acc[i][j][2] + bx, 0.f)),
                                        tf32r(fmaxf(acc[i][j][3] + by, 0.f)));
                *(float2*)(hb + (size_t)r0 * HDIM + col)       = v0;
                *(float2*)(hb + (size_t)(r0 + 8) * HDIM + col) = v1;
            }
        }
    } else {
#pragma unroll
        for (int i = 0; i < 4; i++) {
            int r0 = wm * 64 + i * 16 + g;
            int b0 = rid_s[r0], b1i = rid_s[r0 + 8];
#pragma unroll
            for (int j = 0; j < 8; j++) {
                int col = wn * 64 + j * 8 + 2 * tq;
                float bx = bp[col], by = bp[col + 1];
                if (b0 >= 0)
                    *(float2*)(out + (size_t)b0 * DDIM + n0 + col) =
                        make_float2(acc[i][j][0] + bx, acc[i][j][1] + by);
                if (b1i >= 0)
                    *(float2*)(out + (size_t)b1i * DDIM + n0 + col) =
                        make_float2(acc[i][j][2] + bx, acc[i][j][3] + by);
            }
        }
    }
}

// ---------------- launch ----------------
extern "C" void kernel_launch(void* const* d_in, const int* in_sizes, int n_in,
                              void* d_out, int out_size)
{
    const float* latents = (const float*)d_in[0];
    const float* actions = (const float*)d_in[1];
    const void*  pidx    = d_in[2];
    const float* W1      = (const float*)d_in[3];
    const float* b1      = (const float*)d_in[4];
    const float* W2      = (const float*)d_in[5];
    const float* b2      = (const float*)d_in[6];
    float*       out     = (float*)d_out;

    int B = in_sizes[0] / DDIM;               // 16384
    int gy = B / 128 + PNUM - 1;              // 135: max possible tiles

    cudaFuncSetAttribute(k_mma<1>, cudaFuncAttributeMaxDynamicSharedMemorySize, SMEM_TOTAL);
    cudaFuncSetAttribute(k_mma<2>, cudaFuncAttributeMaxDynamicSharedMemorySize, SMEM_TOTAL);

    k_init<<<1, 32>>>((const int*)pidx, B);
    k_scan<<<(B + 255) / 256, 256>>>(pidx, B);
    k_tw<<<W1BLK + W2BLK, 256>>>(W1, W2);

    k_mma<1><<<dim3(HDIM / 128, gy), 128, SMEM_TOTAL>>>(latents, actions, b1, nullptr);
    k_mma<2><<<dim3(DDIM / 128, gy), 128, SMEM_TOTAL>>>(latents, actions, b2, out);
}

// round 5
// speedup vs baseline: 1.0201x; 1.0201x over previous
#include <cuda_runtime.h>
#include <cstdint>

#define PNUM 8
#define DDIM 512
#define ADIM 64
#define XDIM 576
#define HDIM 1024
#define BCAP 16384
#define MAXT 136

// ---------------- device scratch ----------------
__device__ int d_cursor[PNUM];     // atomic cursors; end state = per-policy counts
__device__ int d_is64;
__device__ int d_row_id[PNUM * BCAP];
__device__ __align__(128) float d_hbuf[(size_t)MAXT * 128 * HDIM];        // 71 MB
__device__ __align__(128) float d_w1t[(size_t)PNUM * HDIM * XDIM];        // [p][n][k], tf32-rounded
__device__ __align__(128) float d_w2t[(size_t)PNUM * DDIM * HDIM];        // [p][n][k], tf32-rounded

// ---------------- helpers ----------------
__device__ __forceinline__ void cpasync16(uint32_t dst, const void* src, int srcsz) {
    asm volatile("cp.async.cg.shared.global [%0], [%1], 16, %2;\n"
                 :: "r"(dst), "l"(src), "r"(srcsz) : "memory");
}
#define CP_COMMIT() asm volatile("cp.async.commit_group;\n" ::: "memory")
#define CP_WAIT(n)  asm volatile("cp.async.wait_group " #n ";\n" ::: "memory")

__device__ __forceinline__ uint32_t smem_u32(const void* p) {
    uint32_t a;
    asm("{ .reg .u64 t; cvta.to.shared.u64 t, %1; cvt.u32.u64 %0, t; }" : "=r"(a) : "l"(p));
    return a;
}
__device__ __forceinline__ float tf32r(float x) {
    uint32_t u;
    asm("cvt.rn.tf32.f32 %0, %1;" : "=r"(u) : "f"(x));
    return __uint_as_float(u);
}
__device__ __forceinline__ uint32_t tf32u(float x) {
    uint32_t u;
    asm("cvt.rn.tf32.f32 %0, %1;" : "=r"(u) : "f"(x));
    return u;
}
__device__ __forceinline__ void ldsm4(uint32_t* r, uint32_t addr) {
    asm volatile("ldmatrix.sync.aligned.m8n8.x4.shared.b16 {%0,%1,%2,%3}, [%4];"
                 : "=r"(r[0]), "=r"(r[1]), "=r"(r[2]), "=r"(r[3]) : "r"(addr));
}
__device__ __forceinline__ void mma_tf32(float* c, const uint32_t* a, uint32_t b0, uint32_t b1) {
    asm volatile(
        "mma.sync.aligned.m16n8k8.row.col.f32.tf32.tf32.f32 "
        "{%0,%1,%2,%3}, {%4,%5,%6,%7}, {%8,%9}, {%0,%1,%2,%3};"
        : "+f"(c[0]), "+f"(c[1]), "+f"(c[2]), "+f"(c[3])
        : "r"(a[0]), "r"(a[1]), "r"(a[2]), "r"(a[3]), "r"(b0), "r"(b1));
}
__device__ __forceinline__ int get_pidx(const void* pi, int b) {
    if (d_is64) return (int)(((const long long*)pi)[b]);
    return ((const int*)pi)[b];
}

// ---------------- setup ----------------
__global__ void k_init(const int* pi32, int B) {
    int t = threadIdx.x;
    if (t < PNUM) d_cursor[t] = 0;
    if (t == 0) {
        int n = B < 64 ? B : 64;
        int is64 = 1;
        for (int i = 0; i < n; i++) {
            int lo = pi32[2 * i], hi = pi32[2 * i + 1];
            if (hi != 0 || lo < 0 || lo >= PNUM) { is64 = 0; break; }
        }
        d_is64 = is64;
    }
}
__global__ void k_scan(const void* __restrict__ pi, int B) {
    int b = blockIdx.x * blockDim.x + threadIdx.x;
    if (b < B) {
        int p = get_pidx(pi, b);
        int pos = atomicAdd(&d_cursor[p], 1);
        d_row_id[p * BCAP + pos] = b;
    }
}

// Transpose + tf32-round weights:
// W1 [p][576k][1024n] -> d_w1t [p][1024n][576k];  W2 [p][1024k][512n] -> d_w2t [p][512n][1024k]
#define W1BLK (PNUM * 18 * 32)
#define W2BLK (PNUM * 32 * 16)
__global__ __launch_bounds__(256) void k_tw(const float* __restrict__ W1,
                                            const float* __restrict__ W2) {
    __shared__ float s[32][33];
    int bid = blockIdx.x;
    int tx = threadIdx.x & 31, ty = threadIdx.x >> 5;
    if (bid < W1BLK) {
        int p = bid / (18 * 32), r = bid % (18 * 32), rt = r / 32, ct = r % 32;
        const float* in = W1 + (size_t)p * XDIM * HDIM;
        float* out = d_w1t + (size_t)p * HDIM * XDIM;
        int r0 = rt * 32, c0 = ct * 32;
#pragma unroll
        for (int i = 0; i < 4; i++)
            s[ty + 8 * i][tx] = in[(size_t)(r0 + ty + 8 * i) * HDIM + c0 + tx];
        __syncthreads();
#pragma unroll
        for (int i = 0; i < 4; i++)
            out[(size_t)(c0 + ty + 8 * i) * XDIM + r0 + tx] = tf32r(s[tx][ty + 8 * i]);
    } else {
        int b2 = bid - W1BLK;
        int p = b2 / (32 * 16), r = b2 % (32 * 16), rt = r / 16, ct = r % 16;
        const float* in = W2 + (size_t)p * HDIM * DDIM;
        float* out = d_w2t + (size_t)p * DDIM * HDIM;
        int r0 = rt * 32, c0 = ct * 32;
#pragma unroll
        for (int i = 0; i < 4; i++)
            s[ty + 8 * i][tx] = in[(size_t)(r0 + ty + 8 * i) * DDIM + c0 + tx];
        __syncthreads();
#pragma unroll
        for (int i = 0; i < 4; i++)
            out[(size_t)(c0 + ty + 8 * i) * HDIM + r0 + tx] = tf32r(s[tx][ty + 8 * i]);
    }
}

// ---------------- SMEM layout ----------------
#define TSTRIDE 36
#define TBYTES  (128 * TSTRIDE * 4)   // 18432
#define STAGE   (2 * TBYTES)          // 36864
#define SMEM_TOTAL (2 * STAGE)        // 73728

// ---------------- tf32 GEMM: 128x128 CTA tile, 8 warps of 64x32, BK=32 ----------------
template <int LAYER>
__global__ __launch_bounds__(256, 2) void k_mma(
    const float* __restrict__ latents, const float* __restrict__ actions,
    const float* __restrict__ bias, float* __restrict__ out)
{
    constexpr int KDIM = (LAYER == 1) ? XDIM : HDIM;
    constexpr int NDIM = (LAYER == 1) ? HDIM : DDIM;
    constexpr int KT   = KDIM / 32;

    extern __shared__ char smem[];
    __shared__ int rid_s[128];
    __shared__ int s_meta[3];   // p, vrows, ridbase
    const uint32_t sb = smem_u32(smem);
    const int tid = threadIdx.x;
    const int t = blockIdx.y;

    if (tid == 0) {
        int acc = 0, p = -1, lt = 0, c = 0;
#pragma unroll
        for (int q = 0; q < PNUM; q++) {
            int cq = d_cursor[q];
            int nt = (cq + 127) >> 7;
            if (p < 0 && t < acc + nt) { p = q; lt = t - acc; c = cq; }
            acc += nt;
        }
        s_meta[0] = p;
        if (p >= 0) {
            int rem = c - lt * 128;
            s_meta[1] = rem < 128 ? rem : 128;
            s_meta[2] = p * BCAP + lt * 128;
        }
    }
    __syncthreads();
    const int p = s_meta[0];
    if (p < 0) return;
    const int vrows = s_meta[1];
    const int ridbase = s_meta[2];
    const int n0 = blockIdx.x * 128;
    const int row0 = t * 128;   // compact h-buffer row base

    if (tid < 128) rid_s[tid] = (tid < vrows) ? d_row_id[ridbase + tid] : -1;
    __syncthreads();

    const float* __restrict__ Wt = (LAYER == 1)
        ? d_w1t + (size_t)p * HDIM * XDIM + (size_t)n0 * XDIM
        : d_w2t + (size_t)p * DDIM * HDIM + (size_t)n0 * HDIM;

    // ---- async tile loader: 128 rows x 8 segs of 16B for A and B ----
    auto load_chunk = [&](int chunk, int slot) {
        const int kc = chunk * 32;
        const uint32_t abase = sb + slot * STAGE;
        const uint32_t bbase = abase + TBYTES;
#pragma unroll
        for (int tt = 0; tt < 4; tt++) {
            int j = tid + tt * 256;
            int row = j >> 3, seg = j & 7;
            uint32_t dst = abase + row * (TSTRIDE * 4) + seg * 16;
            if (LAYER == 1) {
                int b = rid_s[row];
                int k = kc + seg * 4;
                const float* src; int sz;
                if (b < 0) { src = latents; sz = 0; }
                else if (k < DDIM) { src = latents + (size_t)b * DDIM + k; sz = 16; }
                else { src = actions + (size_t)b * ADIM + (k - DDIM); sz = 16; }
                cpasync16(dst, src, sz);
            } else {
                cpasync16(dst, d_hbuf + (size_t)(row0 + row) * HDIM + kc + seg * 4, 16);
            }
        }
#pragma unroll
        for (int tt = 0; tt < 4; tt++) {
            int j = tid + tt * 256;
            int row = j >> 3, seg = j & 7;
            cpasync16(bbase + row * (TSTRIDE * 4) + seg * 16,
                      Wt + (size_t)row * KDIM + kc + seg * 4, 16);
        }
        CP_COMMIT();
    };

    // ---- fragment geometry: 2(m) x 4(n) warp grid, 64x32 warp tiles ----
    const int lane = tid & 31, warp = tid >> 5;
    const int wm = warp >> 2, wn = warp & 3;
    const int g = lane >> 2, tq = lane & 3;
    const uint32_t fo = ((uint32_t)(lane & 15) * TSTRIDE + ((lane & 16) >> 2)) * 4;
    const uint32_t ao = (uint32_t)(wm * 64) * TSTRIDE * 4 + fo;
    const uint32_t bo = (uint32_t)(wn * 32) * TSTRIDE * 4 + fo;

    float acc[4][4][4];
#pragma unroll
    for (int i = 0; i < 4; i++)
#pragma unroll
        for (int j = 0; j < 4; j++)
#pragma unroll
            for (int q = 0; q < 4; q++) acc[i][j][q] = 0.f;

    load_chunk(0, 0);

    for (int c = 0; c < KT; c++) {
        if (c + 1 < KT) { load_chunk(c + 1, (c + 1) & 1); CP_WAIT(1); }
        else            { CP_WAIT(0); }
        __syncthreads();

        const uint32_t Ab = sb + (c & 1) * STAGE;
        const uint32_t Bb = Ab + TBYTES;

#pragma unroll
        for (int ks = 0; ks < 4; ks++) {
            uint32_t a[4][4], b[2][4];
#pragma unroll
            for (int i = 0; i < 4; i++)
                ldsm4(a[i], Ab + ao + (uint32_t)(i * 16 * TSTRIDE + ks * 8) * 4);
            if (LAYER == 1) {
#pragma unroll
                for (int i = 0; i < 4; i++)
#pragma unroll
                    for (int q = 0; q < 4; q++)
                        a[i][q] = tf32u(__uint_as_float(a[i][q]));
            }
#pragma unroll
            for (int jj = 0; jj < 2; jj++)
                ldsm4(b[jj], Bb + bo + (uint32_t)(jj * 16 * TSTRIDE + ks * 8) * 4);
#pragma unroll
            for (int i = 0; i < 4; i++)
#pragma unroll
                for (int jj = 0; jj < 2; jj++) {
                    mma_tf32(acc[i][2 * jj],     a[i], b[jj][0], b[jj][2]);
                    mma_tf32(acc[i][2 * jj + 1], a[i], b[jj][1], b[jj][3]);
                }
        }
        __syncthreads();
    }

    // ---- epilogue ----
    const float* bp = bias + p * NDIM + n0;
    if (LAYER == 1) {
        float* hb = d_hbuf + (size_t)row0 * HDIM + n0;
#pragma unroll
        for (int j = 0; j < 4; j++) {
            int col = wn * 32 + j * 8 + 2 * tq;
            float bx = bp[col], by = bp[col + 1];
#pragma unroll
            for (int i = 0; i < 4; i++) {
                int r0 = wm * 64 + i * 16 + g;
                float2 v0 = make_float2(tf32r(fmaxf(acc[i][j][0] + bx, 0.f)),
                                        tf32r(fmaxf(acc[i][j][1] + by, 0.f)));
                float2 v1 = make_float2(tf32r(fmaxf(acc[i][j][2] + bx, 0.f)),
                                        tf32r(fmaxf(acc[i][j][3] + by, 0.f)));
                *(float2*)(hb + (size_t)r0 * HDIM + col)       = v0;
                *(float2*)(hb + (size_t)(r0 + 8) * HDIM + col) = v1;
            }
        }
    } else {
#pragma unroll
        for (int i = 0; i < 4; i++) {
            int r0 = wm * 64 + i * 16 + g;
            int b0 = rid_s[r0], b1i = rid_s[r0 + 8];
#pragma unroll
            for (int j = 0; j < 4; j++) {
                int col = wn * 32 + j * 8 + 2 * tq;
                float bx = bp[col], by = bp[col + 1];
                if (b0 >= 0)
                    *(float2*)(out + (size_t)b0 * DDIM + n0 + col) =
                        make_float2(acc[i][j][0] + bx, acc[i][j][1] + by);
                if (b1i >= 0)
                    *(float2*)(out + (size_t)b1i * DDIM + n0 + col) =
                        make_float2(acc[i][j][2] + bx, acc[i][j][3] + by);
            }
        }
    }
}

// ---------------- launch ----------------
extern "C" void kernel_launch(void* const* d_in, const int* in_sizes, int n_in,
                              void* d_out, int out_size)
{
    const float* latents = (const float*)d_in[0];
    const float* actions = (const float*)d_in[1];
    const void*  pidx    = d_in[2];
    const float* W1      = (const float*)d_in[3];
    const float* b1      = (const float*)d_in[4];
    const float* W2      = (const float*)d_in[5];
    const float* b2      = (const float*)d_in[6];
    float*       out     = (float*)d_out;

    int B = in_sizes[0] / DDIM;               // 16384
    int gy = B / 128 + PNUM - 1;              // 135: max possible tiles

    cudaFuncSetAttribute(k_mma<1>, cudaFuncAttributeMaxDynamicSharedMemorySize, SMEM_TOTAL);
    cudaFuncSetAttribute(k_mma<2>, cudaFuncAttributeMaxDynamicSharedMemorySize, SMEM_TOTAL);

    k_init<<<1, 32>>>((const int*)pidx, B);
    k_scan<<<(B + 255) / 256, 256>>>(pidx, B);
    k_tw<<<W1BLK + W2BLK, 256>>>(W1, W2);

    k_mma<1><<<dim3(HDIM / 128, gy), 256, SMEM_TOTAL>>>(latents, actions, b1, nullptr);
    k_mma<2><<<dim3(DDIM / 128, gy), 256, SMEM_TOTAL>>>(latents, actions, b2, out);
}